// round 3
// baseline (speedup 1.0000x reference)
#include <cuda_runtime.h>
#include <cstdint>

// ============================================================================
// Problem constants
// ============================================================================
#define M_DIM 4096
#define K_DIM 4096
#define S_DIM 2048
#define N_DIM 16384            // B*S = 8*2048

#define BM 128
#define BN 256
#define BK 32
#define K_ITERS (K_DIM / BK)   // 128
#define STAGES 3

#define THREADS 256            // 8 warps: 2 (m) x 4 (n), warp tile 64x64

// SMEM row stride 40 floats (160B): 40 ≡ 8 (mod 32) -> conflict-free LDS.64
#define SKA 40
#define A_STAGE_ELEMS (BM * SKA)              // 5120
#define B_STAGE_ELEMS (BN * SKA)              // 10240
#define STAGE_ELEMS   (A_STAGE_ELEMS + B_STAGE_ELEMS)   // 15360
#define SMEM_BYTES    (STAGES * STAGE_ELEMS * 4)        // 184320

// ============================================================================
// Scratch (device globals — no runtime allocation allowed)
// g_W / g_X hold tf32-rounded data with each aligned 8-float k-group stored
// PERMUTED as [k0,k4,k1,k5,k2,k6,k3,k7] so the mma fragment pair (t, t+4)
// is adjacent -> single LDS.64 per fragment pair.
// ============================================================================
__device__ __align__(128) float g_W[(size_t)M_DIM * K_DIM];   // 64 MB
__device__ __align__(128) float g_X[(size_t)N_DIM * K_DIM];   // 256 MB

// ============================================================================
// Helpers
// ============================================================================
__device__ __forceinline__ float tf32_rna(float f) {
    float o;
    asm("cvt.rna.tf32.f32 %0, %1;" : "=f"(o) : "f"(f));
    return o;
}

__device__ __forceinline__ uint32_t smem_u32(const void* p) {
    uint32_t a;
    asm("{ .reg .u64 t; cvta.to.shared.u64 t, %1; cvt.u32.u64 %0, t; }"
        : "=r"(a) : "l"(p));
    return a;
}

__device__ __forceinline__ void cp_async16(uint32_t dst, const void* src) {
    asm volatile("cp.async.cg.shared.global [%0], [%1], 16;"
                 :: "r"(dst), "l"(src));
}
__device__ __forceinline__ void cp_commit() {
    asm volatile("cp.async.commit_group;");
}
__device__ __forceinline__ void cp_wait1() {
    asm volatile("cp.async.wait_group 1;");
}

__device__ __forceinline__ uint2 lds64(uint32_t addr) {
    uint2 v;
    asm volatile("ld.shared.v2.u32 {%0,%1}, [%2];"
                 : "=r"(v.x), "=r"(v.y) : "r"(addr));
    return v;
}

__device__ __forceinline__ void mma_tf32(float* c,
                                         uint32_t a0, uint32_t a1,
                                         uint32_t a2, uint32_t a3,
                                         uint32_t b0, uint32_t b1) {
    asm volatile(
        "mma.sync.aligned.m16n8k8.row.col.f32.tf32.tf32.f32 "
        "{%0,%1,%2,%3}, {%4,%5,%6,%7}, {%8,%9}, {%0,%1,%2,%3};"
        : "+f"(c[0]), "+f"(c[1]), "+f"(c[2]), "+f"(c[3])
        : "r"(a0), "r"(a1), "r"(a2), "r"(a3), "r"(b0), "r"(b1));
}

// ============================================================================
// Pre-pass kernels
// ============================================================================
__global__ void scatter_kernel(const float* __restrict__ vals,
                               const int* __restrict__ rows,
                               const int* __restrict__ cols, int nnz) {
    int i = blockIdx.x * blockDim.x + threadIdx.x;
    if (i < nnz) {
        atomicAdd(&g_W[(size_t)rows[i] * K_DIM + cols[i]], vals[i]);
    }
}

// In-place: round W to tf32 and permute each 8-float k-group to
// [k0,k4,k1,k5,k2,k6,k3,k7]. One thread owns one 8-group (no races).
__global__ void round_perm_w_kernel() {
    size_t n8 = (size_t)M_DIM * K_DIM / 8;
    float4* p = reinterpret_cast<float4*>(g_W);
    for (size_t i = blockIdx.x * blockDim.x + threadIdx.x; i < n8;
         i += (size_t)gridDim.x * blockDim.x) {
        float4 v0 = p[2 * i];       // k0..k3
        float4 v1 = p[2 * i + 1];   // k4..k7
        float4 o0, o1;
        o0.x = tf32_rna(v0.x); o0.y = tf32_rna(v1.x);   // k0,k4
        o0.z = tf32_rna(v0.y); o0.w = tf32_rna(v1.y);   // k1,k5
        o1.x = tf32_rna(v0.z); o1.y = tf32_rna(v1.z);   // k2,k6
        o1.z = tf32_rna(v0.w); o1.w = tf32_rna(v1.w);   // k3,k7
        p[2 * i]     = o0;
        p[2 * i + 1] = o1;
    }
}

// Copy x -> g_X with tf32 rounding + same k-group permutation.
__global__ void conv_perm_x_kernel(const float* __restrict__ x) {
    size_t n8 = (size_t)N_DIM * K_DIM / 8;
    const float4* src = reinterpret_cast<const float4*>(x);
    float4* dst = reinterpret_cast<float4*>(g_X);
    for (size_t i = blockIdx.x * blockDim.x + threadIdx.x; i < n8;
         i += (size_t)gridDim.x * blockDim.x) {
        float4 v0 = src[2 * i];
        float4 v1 = src[2 * i + 1];
        float4 o0, o1;
        o0.x = tf32_rna(v0.x); o0.y = tf32_rna(v1.x);
        o0.z = tf32_rna(v0.y); o0.w = tf32_rna(v1.y);
        o1.x = tf32_rna(v0.z); o1.y = tf32_rna(v1.z);
        o1.z = tf32_rna(v0.w); o1.w = tf32_rna(v1.w);
        dst[2 * i]     = o0;
        dst[2 * i + 1] = o1;
    }
}

// ============================================================================
// tf32 mma.sync GEMM: out[b,m,s] = sum_k W[m,k] * X[n,k] + bias[s],  n=b*2048+s
// 8 warps, warp tile 64x64 (4x8 grid of m16n8k8), CTA tile 128x256.
// ============================================================================
__global__ void __launch_bounds__(THREADS, 1) gemm_kernel(
    const float* __restrict__ bias, float* __restrict__ out)
{
    extern __shared__ uint32_t smem[];
    const uint32_t sbase = smem_u32(smem);

    const int tid  = threadIdx.x;
    const int wid  = tid >> 5;
    const int lane = tid & 31;
    const int g = lane >> 2;        // fragment row group 0..7
    const int t = lane & 3;         // fragment col group 0..3
    const int wm = wid & 1;         // warp m index 0..1
    const int wn = wid >> 1;        // warp n index 0..3

    // CTA tile mapping: bid = mt + 32*nt (a wave covers all m-tiles -> A reuse)
    const int mt = blockIdx.x & 31;
    const int nt = blockIdx.x >> 5;
    const int m0 = mt * BM;
    const int n0 = nt * BN;

    // cp.async assignments: 16B chunks. A: 1024 chunks -> 4/thread,
    // B: 2048 chunks -> 8/thread.
    int a_row[4], a_seg[4];
    int b_row[8], b_seg[8];
#pragma unroll
    for (int i = 0; i < 4; i++) {
        int c = tid + i * THREADS;
        a_row[i] = c >> 3; a_seg[i] = c & 7;
    }
#pragma unroll
    for (int i = 0; i < 8; i++) {
        int c = tid + i * THREADS;
        b_row[i] = c >> 3; b_seg[i] = c & 7;
    }

    const float* Abase = g_W + (size_t)m0 * K_DIM;
    const float* Bbase = g_X + (size_t)n0 * K_DIM;

    auto load_stage = [&](int stage, int ks) {
        uint32_t so = sbase + (uint32_t)(stage * STAGE_ELEMS) * 4u;
#pragma unroll
        for (int i = 0; i < 4; i++) {
            cp_async16(so + (uint32_t)(a_row[i] * SKA + a_seg[i] * 4) * 4u,
                       Abase + (size_t)a_row[i] * K_DIM + ks * BK + a_seg[i] * 4);
        }
#pragma unroll
        for (int i = 0; i < 8; i++) {
            cp_async16(so + (uint32_t)(A_STAGE_ELEMS + b_row[i] * SKA + b_seg[i] * 4) * 4u,
                       Bbase + (size_t)b_row[i] * K_DIM + ks * BK + b_seg[i] * 4);
        }
    };

    float acc[4][8][4];
#pragma unroll
    for (int i = 0; i < 4; i++)
#pragma unroll
        for (int j = 0; j < 8; j++)
#pragma unroll
            for (int r = 0; r < 4; r++) acc[i][j][r] = 0.0f;

    // Precomputed SMEM byte offsets (within a stage) for fragment loads.
    // A row for mi: wm*64 + mi*16 + g  (and +8); col word: kk*8 + 2t.
    const uint32_t a_off0 = sbase + (uint32_t)(((wm * 64 + g) * SKA) + 2 * t) * 4u;
    const uint32_t b_off0 = sbase + (uint32_t)((A_STAGE_ELEMS + (wn * 64 + g) * SKA) + 2 * t) * 4u;

    // prologue: fill STAGES-1 stages
    load_stage(0, 0); cp_commit();
    load_stage(1, 1); cp_commit();

    for (int k = 0; k < K_ITERS; k++) {
        cp_wait1();
        __syncthreads();

        if (k + 2 < K_ITERS) load_stage((k + 2) % STAGES, k + 2);
        cp_commit();

        const uint32_t stoff = (uint32_t)((k % STAGES) * STAGE_ELEMS) * 4u;
        const uint32_t aS = a_off0 + stoff;
        const uint32_t bS = b_off0 + stoff;

#pragma unroll
        for (int kk = 0; kk < 4; kk++) {
            // A fragments: 4 mi blocks, 2x LDS.64 each
            uint2 alo[4], ahi[4];
#pragma unroll
            for (int mi = 0; mi < 4; mi++) {
                uint32_t base = aS + (uint32_t)(mi * 16 * SKA + kk * 8) * 4u;
                alo[mi] = lds64(base);                       // (g,   t), (g,   t+4)
                ahi[mi] = lds64(base + (uint32_t)(8 * SKA) * 4u); // (g+8, t), (g+8, t+4)
            }
#pragma unroll
            for (int ni = 0; ni < 8; ni++) {
                uint2 b = lds64(bS + (uint32_t)(ni * 8 * SKA + kk * 8) * 4u);
#pragma unroll
                for (int mi = 0; mi < 4; mi++) {
                    mma_tf32(acc[mi][ni], alo[mi].x, ahi[mi].x,
                             alo[mi].y, ahi[mi].y, b.x, b.y);
                }
            }
        }
    }

    // ------------------------------------------------------------------------
    // Epilogue: out[b, m, s] = acc + bias[s]; CTA tile lies in one batch
    // ------------------------------------------------------------------------
    const int b   = n0 >> 11;        // n0 / 2048
    const int s0c = n0 & 2047;
    float* obase = out + (size_t)b * M_DIM * S_DIM;

#pragma unroll
    for (int mi = 0; mi < 4; mi++) {
#pragma unroll
        for (int ni = 0; ni < 8; ni++) {
            int sl = s0c + wn * 64 + ni * 8 + 2 * t;
            float2 bv = *reinterpret_cast<const float2*>(bias + sl);
            int m = m0 + wm * 64 + mi * 16 + g;

            float2 v0;
            v0.x = acc[mi][ni][0] + bv.x;
            v0.y = acc[mi][ni][1] + bv.y;
            *reinterpret_cast<float2*>(obase + (size_t)m * S_DIM + sl) = v0;

            float2 v1;
            v1.x = acc[mi][ni][2] + bv.x;
            v1.y = acc[mi][ni][3] + bv.y;
            *reinterpret_cast<float2*>(obase + (size_t)(m + 8) * S_DIM + sl) = v1;
        }
    }
}

// ============================================================================
// Host launch
// ============================================================================
extern "C" void kernel_launch(void* const* d_in, const int* in_sizes, int n_in,
                              void* d_out, int out_size) {
    const float* x      = (const float*)d_in[0];
    const float* values = (const float*)d_in[1];
    const float* bias   = (const float*)d_in[2];
    const int* row_ids  = (const int*)d_in[3];
    const int* col_idx  = (const int*)d_in[4];
    int nnz = in_sizes[1];
    float* out = (float*)d_out;

    void* wptr = nullptr;
    cudaGetSymbolAddress(&wptr, g_W);

    // 1) zero W (each replay re-accumulates from zero)
    cudaMemsetAsync(wptr, 0, (size_t)M_DIM * K_DIM * sizeof(float));

    // 2) scatter-add COO values into dense W (natural layout)
    scatter_kernel<<<(nnz + 255) / 256, 256>>>(values, row_ids, col_idx, nnz);

    // 3) tf32-round + k-group permute (in place for W, copy for x)
    round_perm_w_kernel<<<2048, 256>>>();
    conv_perm_x_kernel<<<8192, 256>>>(x);

    // 4) GEMM
    static bool attr_set = false;
    if (!attr_set) {
        cudaFuncSetAttribute(gemm_kernel,
                             cudaFuncAttributeMaxDynamicSharedMemorySize,
                             SMEM_BYTES);
        attr_set = true;
    }
    gemm_kernel<<<(M_DIM / BM) * (N_DIM / BN), THREADS, SMEM_BYTES>>>(bias, out);
}

// round 4
// speedup vs baseline: 1.0803x; 1.0803x over previous
#include <cuda_runtime.h>
#include <cstdint>

// ============================================================================
// Problem constants
// ============================================================================
#define M_DIM 4096
#define K_DIM 4096
#define S_DIM 2048
#define N_DIM 16384            // B*S = 8*2048

#define BM 128
#define BN 256
#define BK 32
#define K_ITERS (K_DIM / BK)   // 128
#define STAGES 4

#define THREADS 288            // 8 compute warps (2m x 4n, warp tile 64x64) + 1 producer

// Stage: A 128x32 fp32 (16KB) + B 256x32 fp32 (32KB), both packed 32 words/row
#define A_STAGE_BYTES 16384
#define B_STAGE_BYTES 32768
#define STAGE_BYTES   (A_STAGE_BYTES + B_STAGE_BYTES)   // 49152
#define SMEM_STAGE0   1024
#define SMEM_BYTES    (SMEM_STAGE0 + STAGES * STAGE_BYTES)  // 197632

// mbarriers: full[s] at s*16, empty[s] at s*16+8
#define MB_FULL(s)  (s * 16)
#define MB_EMPTY(s) (s * 16 + 8)

// ============================================================================
// Scratch (device globals — no runtime allocation allowed)
//
// Blocked + swizzled staging layout, unit = 32-word (128B) row chunk:
//   g_W[kb][m][32], g_X[kb][n][32]   (kb = k/32)
// Within a 32-word chunk, logical k index j (0..31) is stored at:
//   kk = j>>3, jj = j&7
//   p  = jj<4 ? 2*jj : 2*(jj-4)+1          (pair perm: [k0,k4,k1,k5,...])
//   c  = ((kk ^ (row & 3)) << 3) | p       (XOR swizzle -> conflict-free LDS.64)
// ============================================================================
__device__ __align__(128) float g_W[(size_t)M_DIM * K_DIM];   // 64 MB
__device__ __align__(128) float g_X[(size_t)N_DIM * K_DIM];   // 256 MB

// ============================================================================
// Helpers
// ============================================================================
__device__ __forceinline__ float tf32_rna(float f) {
    float o;
    asm("cvt.rna.tf32.f32 %0, %1;" : "=f"(o) : "f"(f));
    return o;
}

__device__ __forceinline__ uint32_t smem_u32(const void* p) {
    uint32_t a;
    asm("{ .reg .u64 t; cvta.to.shared.u64 t, %1; cvt.u32.u64 %0, t; }"
        : "=r"(a) : "l"(p));
    return a;
}

__device__ __forceinline__ uint32_t elect_one_pred() {
    uint32_t pred;
    asm volatile(
        "{\n\t.reg .pred p;\n\telect.sync _|p, 0xFFFFFFFF;\n\tselp.b32 %0, 1, 0, p;\n\t}"
        : "=r"(pred));
    return pred;
}

__device__ __forceinline__ uint2 lds64(uint32_t addr) {
    uint2 v;
    asm volatile("ld.shared.v2.u32 {%0,%1}, [%2];"
                 : "=r"(v.x), "=r"(v.y) : "r"(addr));
    return v;
}

__device__ __forceinline__ void mma_tf32(float* c,
                                         uint32_t a0, uint32_t a1,
                                         uint32_t a2, uint32_t a3,
                                         uint32_t b0, uint32_t b1) {
    asm volatile(
        "mma.sync.aligned.m16n8k8.row.col.f32.tf32.tf32.f32 "
        "{%0,%1,%2,%3}, {%4,%5,%6,%7}, {%8,%9}, {%0,%1,%2,%3};"
        : "+f"(c[0]), "+f"(c[1]), "+f"(c[2]), "+f"(c[3])
        : "r"(a0), "r"(a1), "r"(a2), "r"(a3), "r"(b0), "r"(b1));
}

#define MBARRIER_INIT(mbar, count) \
    asm volatile("mbarrier.init.shared.b64 [%0], %1;" \
                 :: "r"((uint32_t)(mbar)), "r"((uint32_t)(count)) : "memory")

#define MBARRIER_ARRIVE(mbar) \
    asm volatile("mbarrier.arrive.shared.b64 _, [%0];" \
                 :: "r"((uint32_t)(mbar)) : "memory")

#define MBARRIER_EXPECT_TX(mbar, tx_bytes) \
    asm volatile("mbarrier.arrive.expect_tx.shared.b64 _, [%0], %1;" \
                 :: "r"((uint32_t)(mbar)), "r"((uint32_t)(tx_bytes)) : "memory")

#define MBARRIER_WAIT_PARITY(mbar, parity) do {                                   \
    uint32_t _mbar = (uint32_t)(mbar);                                            \
    uint32_t _par = (uint32_t)(parity);                                           \
    uint32_t _done;                                                               \
    asm volatile(                                                                 \
        "{\n\t.reg .pred p;\n\t"                                                  \
        "mbarrier.try_wait.parity.acquire.cta.shared::cta.b64 p, [%1], %2;\n\t"   \
        "selp.b32 %0, 1, 0, p;\n\t}"                                              \
        : "=r"(_done) : "r"(_mbar), "r"(_par) : "memory");                        \
    if (!_done) {                                                                 \
        asm volatile(                                                             \
            "{\n\t.reg .pred P1;\n\t"                                             \
            "WAIT_LOOP_%=:\n\t"                                                   \
            "mbarrier.try_wait.parity.acquire.cta.shared::cta.b64 P1, [%0], %1, 0x989680;\n\t" \
            "@P1 bra.uni WAIT_DONE_%=;\n\t"                                       \
            "bra.uni WAIT_LOOP_%=;\n\t"                                           \
            "WAIT_DONE_%=:\n\t}"                                                  \
            :: "r"(_mbar), "r"(_par) : "memory");                                 \
    }                                                                             \
} while (0)

#define MBARRIER_WAIT_PARITY_RELAXED(mbar, parity) do {                           \
    uint32_t _mbar = (uint32_t)(mbar);                                            \
    uint32_t _par = (uint32_t)(parity);                                           \
    uint32_t _done;                                                               \
    asm volatile(                                                                 \
        "{\n\t.reg .pred p;\n\t"                                                  \
        "mbarrier.try_wait.parity.relaxed.cta.shared::cta.b64 p, [%1], %2, 0x989680;\n\t" \
        "selp.b32 %0, 1, 0, p;\n\t}"                                              \
        : "=r"(_done) : "r"(_mbar), "r"(_par) : "memory");                        \
    if (!_done) {                                                                 \
        asm volatile(                                                             \
            "{\n\t.reg .pred P1;\n\t"                                             \
            "WAIT_LOOP_%=:\n\t"                                                   \
            "mbarrier.try_wait.parity.relaxed.cta.shared::cta.b64 P1, [%0], %1, 0x989680;\n\t" \
            "@P1 bra.uni WAIT_DONE_%=;\n\t"                                       \
            "bra.uni WAIT_LOOP_%=;\n\t"                                           \
            "WAIT_DONE_%=:\n\t}"                                                  \
            :: "r"(_mbar), "r"(_par) : "memory");                                 \
    }                                                                             \
} while (0)

#define BULK_G2S(dst_smem, src_gmem, nbytes, mbar)                                \
    asm volatile(                                                                 \
        "cp.async.bulk.shared::cta.global.mbarrier::complete_tx::bytes "          \
        "[%0], [%1], %2, [%3];"                                                   \
        :: "r"((uint32_t)(dst_smem)), "l"(src_gmem),                              \
           "r"((uint32_t)(nbytes)), "r"((uint32_t)(mbar)) : "memory")

// ============================================================================
// Pre-pass kernels
// ============================================================================
__global__ void scatter_kernel(const float* __restrict__ vals,
                               const int* __restrict__ rows,
                               const int* __restrict__ cols, int nnz) {
    int i = blockIdx.x * blockDim.x + threadIdx.x;
    if (i < nnz) {
        int r = rows[i], c = cols[i];
        int kb = c >> 5, j = c & 31, kk = j >> 3, jj = j & 7;
        int p = (jj < 4) ? (jj << 1) : (((jj - 4) << 1) | 1);
        int cc = ((kk ^ (r & 3)) << 3) | p;
        atomicAdd(&g_W[(size_t)kb * (M_DIM * 32) + (size_t)r * 32 + cc], vals[i]);
    }
}

// Elementwise tf32-round of W (layout-independent, in place).
__global__ void round_w_kernel() {
    size_t n4 = (size_t)M_DIM * K_DIM / 4;
    float4* p = reinterpret_cast<float4*>(g_W);
    for (size_t i = blockIdx.x * blockDim.x + threadIdx.x; i < n4;
         i += (size_t)gridDim.x * blockDim.x) {
        float4 v = p[i];
        v.x = tf32_rna(v.x); v.y = tf32_rna(v.y);
        v.z = tf32_rna(v.z); v.w = tf32_rna(v.w);
        p[i] = v;
    }
}

// x -> g_X: tf32 round + k-blocked + pair-perm + XOR swizzle.
// One thread per 8-k group.
__global__ void conv_x_kernel(const float* __restrict__ x) {
    size_t ngroups = (size_t)N_DIM * (K_DIM / 8);
    for (size_t i = blockIdx.x * blockDim.x + threadIdx.x; i < ngroups;
         i += (size_t)gridDim.x * blockDim.x) {
        int n  = (int)(i >> 9);            // K/8 = 512 groups per row
        int k8 = (int)(i & 511);
        int kb = k8 >> 2, kk = k8 & 3;
        const float4* src = reinterpret_cast<const float4*>(x + (size_t)n * K_DIM + k8 * 8);
        float4 v0 = src[0];                // k0..k3
        float4 v1 = src[1];                // k4..k7
        float4 o0, o1;
        o0.x = tf32_rna(v0.x); o0.y = tf32_rna(v1.x);   // k0,k4
        o0.z = tf32_rna(v0.y); o0.w = tf32_rna(v1.y);   // k1,k5
        o1.x = tf32_rna(v0.z); o1.y = tf32_rna(v1.z);   // k2,k6
        o1.z = tf32_rna(v0.w); o1.w = tf32_rna(v1.w);   // k3,k7
        float* dst = g_X + (size_t)kb * (N_DIM * 32) + (size_t)n * 32
                         + ((kk ^ (n & 3)) << 3);
        reinterpret_cast<float4*>(dst)[0] = o0;
        reinterpret_cast<float4*>(dst)[1] = o1;
    }
}

// ============================================================================
// Warp-specialized tf32 GEMM with cp.async.bulk producer.
// out[b,m,s] = sum_k W[m,k] * X[n,k] + bias[s],  n = b*2048 + s
// ============================================================================
__global__ void __launch_bounds__(THREADS, 1) gemm_kernel(
    const float* __restrict__ bias, float* __restrict__ out)
{
    extern __shared__ uint32_t smem[];
    const uint32_t sbase = smem_u32(smem);

    const int tid  = threadIdx.x;
    const int wid  = tid >> 5;
    const int lane = tid & 31;

    // CTA tile mapping: bid = mt + 32*nt (wave covers all m-tiles -> A reuse)
    const int mt = blockIdx.x & 31;
    const int nt = blockIdx.x >> 5;
    const int m0 = mt * BM;
    const int n0 = nt * BN;

    if (tid == 0) {
        #pragma unroll
        for (int s = 0; s < STAGES; s++) {
            MBARRIER_INIT(sbase + MB_FULL(s), 1);
            MBARRIER_INIT(sbase + MB_EMPTY(s), 8);
        }
    }
    __syncthreads();

    if (wid == 8) {
        // ------------------------- Producer warp -------------------------
        if (elect_one_pred()) {
            const float* Asrc0 = g_W + (size_t)m0 * 32;
            const float* Bsrc0 = g_X + (size_t)n0 * 32;
            int stage = 0, ph = 1;   // fresh barriers: parity-1 waits pass
            for (int k = 0; k < K_ITERS; k++) {
                MBARRIER_WAIT_PARITY_RELAXED(sbase + MB_EMPTY(stage), ph);
                uint32_t full = sbase + MB_FULL(stage);
                uint32_t dst  = sbase + SMEM_STAGE0 + stage * STAGE_BYTES;
                MBARRIER_EXPECT_TX(full, STAGE_BYTES);
                BULK_G2S(dst, Asrc0 + (size_t)k * (M_DIM * 32),
                         A_STAGE_BYTES, full);
                BULK_G2S(dst + A_STAGE_BYTES, Bsrc0 + (size_t)k * (N_DIM * 32),
                         B_STAGE_BYTES, full);
                if (++stage == STAGES) { stage = 0; ph ^= 1; }
            }
        }
        return;
    }

    // --------------------------- Consumer warps ---------------------------
    const int g  = lane >> 2;       // fragment row group 0..7
    const int t  = lane & 3;        // fragment col group 0..3
    const int gx = g & 3;           // XOR swizzle key
    const int wm = wid & 1;         // warp m index 0..1
    const int wn = wid >> 1;        // warp n index 0..3

    // Byte offsets within a stage (row stride 128B = 32 words):
    const uint32_t aBase = (uint32_t)((wm * 64 + g) * 128 + t * 8);
    const uint32_t bBase = (uint32_t)(A_STAGE_BYTES + (wn * 64 + g) * 128 + t * 8);

    float acc[4][8][4];
#pragma unroll
    for (int i = 0; i < 4; i++)
#pragma unroll
        for (int j = 0; j < 8; j++)
#pragma unroll
            for (int r = 0; r < 4; r++) acc[i][j][r] = 0.0f;

    int stage = 0, ph = 0;
    for (int k = 0; k < K_ITERS; k++) {
        MBARRIER_WAIT_PARITY(sbase + MB_FULL(stage), ph);
        const uint32_t st = sbase + SMEM_STAGE0 + stage * STAGE_BYTES;
        const uint32_t aS = st + aBase;
        const uint32_t bS = st + bBase;

#pragma unroll
        for (int kk = 0; kk < 4; kk++) {
            const uint32_t kx = (uint32_t)((kk ^ gx) << 5);   // xor-group: 32B step
            uint2 alo[4], ahi[4];
#pragma unroll
            for (int mi = 0; mi < 4; mi++) {
                uint32_t base = aS + mi * 2048 + kx;          // mi*16 rows * 128B
                alo[mi] = lds64(base);                        // (g,   t), (g,   t+4)
                ahi[mi] = lds64(base + 1024);                 // (g+8, t), (g+8, t+4)
            }
#pragma unroll
            for (int ni = 0; ni < 8; ni++) {
                uint2 b = lds64(bS + ni * 1024 + kx);         // ni*8 rows * 128B
#pragma unroll
                for (int mi = 0; mi < 4; mi++) {
                    mma_tf32(acc[mi][ni], alo[mi].x, ahi[mi].x,
                             alo[mi].y, ahi[mi].y, b.x, b.y);
                }
            }
        }

        __syncwarp();
        if (lane == 0) MBARRIER_ARRIVE(sbase + MB_EMPTY(stage));
        if (++stage == STAGES) { stage = 0; ph ^= 1; }
    }

    // ------------------------------------------------------------------------
    // Epilogue: out[b, m, s] = acc + bias[s]; CTA tile lies in one batch
    // ------------------------------------------------------------------------
    const int b   = n0 >> 11;        // n0 / 2048
    const int s0c = n0 & 2047;
    float* obase = out + (size_t)b * M_DIM * S_DIM;

#pragma unroll
    for (int mi = 0; mi < 4; mi++) {
#pragma unroll
        for (int ni = 0; ni < 8; ni++) {
            int sl = s0c + wn * 64 + ni * 8 + 2 * t;
            float2 bv = *reinterpret_cast<const float2*>(bias + sl);
            int m = m0 + wm * 64 + mi * 16 + g;

            float2 v0;
            v0.x = acc[mi][ni][0] + bv.x;
            v0.y = acc[mi][ni][1] + bv.y;
            *reinterpret_cast<float2*>(obase + (size_t)m * S_DIM + sl) = v0;

            float2 v1;
            v1.x = acc[mi][ni][2] + bv.x;
            v1.y = acc[mi][ni][3] + bv.y;
            *reinterpret_cast<float2*>(obase + (size_t)(m + 8) * S_DIM + sl) = v1;
        }
    }
}

// ============================================================================
// Host launch
// ============================================================================
extern "C" void kernel_launch(void* const* d_in, const int* in_sizes, int n_in,
                              void* d_out, int out_size) {
    const float* x      = (const float*)d_in[0];
    const float* values = (const float*)d_in[1];
    const float* bias   = (const float*)d_in[2];
    const int* row_ids  = (const int*)d_in[3];
    const int* col_idx  = (const int*)d_in[4];
    int nnz = in_sizes[1];
    float* out = (float*)d_out;

    void* wptr = nullptr;
    cudaGetSymbolAddress(&wptr, g_W);

    // 1) zero W (each replay re-accumulates from zero)
    cudaMemsetAsync(wptr, 0, (size_t)M_DIM * K_DIM * sizeof(float));

    // 2) scatter-add COO values directly into blocked+swizzled W
    scatter_kernel<<<(nnz + 255) / 256, 256>>>(values, row_ids, col_idx, nnz);

    // 3) tf32-round W in place; build blocked+swizzled tf32 X
    round_w_kernel<<<2048, 256>>>();
    conv_x_kernel<<<4096, 256>>>(x);

    // 4) GEMM
    cudaFuncSetAttribute(gemm_kernel,
                         cudaFuncAttributeMaxDynamicSharedMemorySize,
                         SMEM_BYTES);
    gemm_kernel<<<(M_DIM / BM) * (N_DIM / BN), THREADS, SMEM_BYTES>>>(bias, out);
}

// round 5
// speedup vs baseline: 1.1102x; 1.0276x over previous
#include <cuda_runtime.h>
#include <cstdint>

// ============================================================================
// Problem constants
// ============================================================================
#define M_DIM 4096
#define K_DIM 4096
#define S_DIM 2048
#define N_DIM 16384            // B*S = 8*2048

#define BM 128
#define BN 256
#define BK 32
#define K_ITERS (K_DIM / BK)   // 128
#define STAGES 4
#define K_OUTER (K_ITERS / STAGES)   // 32

#define THREADS 288            // 8 compute warps (2m x 4n, warp tile 64x64) + 1 producer

// Stage: A 128x32 fp32 (16KB) + B 256x32 fp32 (32KB), both packed 32 words/row
#define A_STAGE_BYTES 16384
#define B_STAGE_BYTES 32768
#define STAGE_BYTES   (A_STAGE_BYTES + B_STAGE_BYTES)   // 49152
#define SMEM_STAGE0   1024
#define SMEM_BYTES    (SMEM_STAGE0 + STAGES * STAGE_BYTES)  // 197632

// mbarriers: full[s] at s*16, empty[s] at s*16+8
#define MB_FULL(s)  (s * 16)
#define MB_EMPTY(s) (s * 16 + 8)

// ============================================================================
// Scratch (device globals — no runtime allocation allowed)
//
// Blocked + swizzled staging layout, unit = 32-word (128B) row chunk:
//   g_W[kb][m][32], g_X[kb][n][32]   (kb = k/32)
// Within a 32-word chunk, logical k index j (0..31) is stored at:
//   kk = j>>3, jj = j&7
//   p  = jj<4 ? 2*jj : 2*(jj-4)+1          (pair perm: [k0,k4,k1,k5,...])
//   c  = ((kk ^ (row & 3)) << 3) | p       (XOR swizzle -> conflict-free LDS.64)
// ============================================================================
__device__ __align__(128) float g_W[(size_t)M_DIM * K_DIM];   // 64 MB
__device__ __align__(128) float g_X[(size_t)N_DIM * K_DIM];   // 256 MB

// ============================================================================
// Helpers
// ============================================================================
__device__ __forceinline__ float tf32_rna(float f) {
    float o;
    asm("cvt.rna.tf32.f32 %0, %1;" : "=f"(o) : "f"(f));
    return o;
}

__device__ __forceinline__ uint32_t smem_u32(const void* p) {
    uint32_t a;
    asm("{ .reg .u64 t; cvta.to.shared.u64 t, %1; cvt.u32.u64 %0, t; }"
        : "=r"(a) : "l"(p));
    return a;
}

__device__ __forceinline__ uint32_t elect_one_pred() {
    uint32_t pred;
    asm volatile(
        "{\n\t.reg .pred p;\n\telect.sync _|p, 0xFFFFFFFF;\n\tselp.b32 %0, 1, 0, p;\n\t}"
        : "=r"(pred));
    return pred;
}

__device__ __forceinline__ uint2 lds64(uint32_t addr, uint32_t imm) {
    uint2 v;
    asm volatile("ld.shared.v2.u32 {%0,%1}, [%2];"
                 : "=r"(v.x), "=r"(v.y) : "r"(addr + imm));
    return v;
}

__device__ __forceinline__ void mma_tf32(float* c,
                                         uint32_t a0, uint32_t a1,
                                         uint32_t a2, uint32_t a3,
                                         uint32_t b0, uint32_t b1) {
    asm volatile(
        "mma.sync.aligned.m16n8k8.row.col.f32.tf32.tf32.f32 "
        "{%0,%1,%2,%3}, {%4,%5,%6,%7}, {%8,%9}, {%0,%1,%2,%3};"
        : "+f"(c[0]), "+f"(c[1]), "+f"(c[2]), "+f"(c[3])
        : "r"(a0), "r"(a1), "r"(a2), "r"(a3), "r"(b0), "r"(b1));
}

#define MBARRIER_INIT(mbar, count) \
    asm volatile("mbarrier.init.shared.b64 [%0], %1;" \
                 :: "r"((uint32_t)(mbar)), "r"((uint32_t)(count)) : "memory")

#define MBARRIER_ARRIVE(mbar) \
    asm volatile("mbarrier.arrive.shared.b64 _, [%0];" \
                 :: "r"((uint32_t)(mbar)) : "memory")

#define MBARRIER_EXPECT_TX(mbar, tx_bytes) \
    asm volatile("mbarrier.arrive.expect_tx.shared.b64 _, [%0], %1;" \
                 :: "r"((uint32_t)(mbar)), "r"((uint32_t)(tx_bytes)) : "memory")

#define MBARRIER_WAIT_PARITY(mbar, parity) do {                                   \
    uint32_t _mbar = (uint32_t)(mbar);                                            \
    uint32_t _par = (uint32_t)(parity);                                           \
    uint32_t _done;                                                               \
    asm volatile(                                                                 \
        "{\n\t.reg .pred p;\n\t"                                                  \
        "mbarrier.try_wait.parity.acquire.cta.shared::cta.b64 p, [%1], %2;\n\t"   \
        "selp.b32 %0, 1, 0, p;\n\t}"                                              \
        : "=r"(_done) : "r"(_mbar), "r"(_par) : "memory");                        \
    if (!_done) {                                                                 \
        asm volatile(                                                             \
            "{\n\t.reg .pred P1;\n\t"                                             \
            "WAIT_LOOP_%=:\n\t"                                                   \
            "mbarrier.try_wait.parity.acquire.cta.shared::cta.b64 P1, [%0], %1, 0x989680;\n\t" \
            "@P1 bra.uni WAIT_DONE_%=;\n\t"                                       \
            "bra.uni WAIT_LOOP_%=;\n\t"                                           \
            "WAIT_DONE_%=:\n\t}"                                                  \
            :: "r"(_mbar), "r"(_par) : "memory");                                 \
    }                                                                             \
} while (0)

#define MBARRIER_WAIT_PARITY_RELAXED(mbar, parity) do {                           \
    uint32_t _mbar = (uint32_t)(mbar);                                            \
    uint32_t _par = (uint32_t)(parity);                                           \
    uint32_t _done;                                                               \
    asm volatile(                                                                 \
        "{\n\t.reg .pred p;\n\t"                                                  \
        "mbarrier.try_wait.parity.relaxed.cta.shared::cta.b64 p, [%1], %2, 0x989680;\n\t" \
        "selp.b32 %0, 1, 0, p;\n\t}"                                              \
        : "=r"(_done) : "r"(_mbar), "r"(_par) : "memory");                        \
    if (!_done) {                                                                 \
        asm volatile(                                                             \
            "{\n\t.reg .pred P1;\n\t"                                             \
            "WAIT_LOOP_%=:\n\t"                                                   \
            "mbarrier.try_wait.parity.relaxed.cta.shared::cta.b64 P1, [%0], %1, 0x989680;\n\t" \
            "@P1 bra.uni WAIT_DONE_%=;\n\t"                                       \
            "bra.uni WAIT_LOOP_%=;\n\t"                                           \
            "WAIT_DONE_%=:\n\t}"                                                  \
            :: "r"(_mbar), "r"(_par) : "memory");                                 \
    }                                                                             \
} while (0)

#define BULK_G2S(dst_smem, src_gmem, nbytes, mbar)                                \
    asm volatile(                                                                 \
        "cp.async.bulk.shared::cta.global.mbarrier::complete_tx::bytes "          \
        "[%0], [%1], %2, [%3];"                                                   \
        :: "r"((uint32_t)(dst_smem)), "l"(src_gmem),                              \
           "r"((uint32_t)(nbytes)), "r"((uint32_t)(mbar)) : "memory")

// ============================================================================
// Pre-pass kernels
// ============================================================================
__global__ void scatter_kernel(const float* __restrict__ vals,
                               const int* __restrict__ rows,
                               const int* __restrict__ cols, int nnz) {
    int i = blockIdx.x * blockDim.x + threadIdx.x;
    if (i < nnz) {
        int r = rows[i], c = cols[i];
        int kb = c >> 5, j = c & 31, kk = j >> 3, jj = j & 7;
        int p = (jj < 4) ? (jj << 1) : (((jj - 4) << 1) | 1);
        int cc = ((kk ^ (r & 3)) << 3) | p;
        atomicAdd(&g_W[(size_t)kb * (M_DIM * 32) + (size_t)r * 32 + cc], vals[i]);
    }
}

// Elementwise tf32-round of W (layout-independent, in place).
__global__ void round_w_kernel() {
    size_t n4 = (size_t)M_DIM * K_DIM / 4;
    float4* p = reinterpret_cast<float4*>(g_W);
    for (size_t i = blockIdx.x * blockDim.x + threadIdx.x; i < n4;
         i += (size_t)gridDim.x * blockDim.x) {
        float4 v = p[i];
        v.x = tf32_rna(v.x); v.y = tf32_rna(v.y);
        v.z = tf32_rna(v.z); v.w = tf32_rna(v.w);
        p[i] = v;
    }
}

// x -> g_X: tf32 round + k-blocked + pair-perm + XOR swizzle.
__global__ void conv_x_kernel(const float* __restrict__ x) {
    size_t ngroups = (size_t)N_DIM * (K_DIM / 8);
    for (size_t i = blockIdx.x * blockDim.x + threadIdx.x; i < ngroups;
         i += (size_t)gridDim.x * blockDim.x) {
        int n  = (int)(i >> 9);            // K/8 = 512 groups per row
        int k8 = (int)(i & 511);
        int kb = k8 >> 2, kk = k8 & 3;
        const float4* src = reinterpret_cast<const float4*>(x + (size_t)n * K_DIM + k8 * 8);
        float4 v0 = src[0];                // k0..k3
        float4 v1 = src[1];                // k4..k7
        float4 o0, o1;
        o0.x = tf32_rna(v0.x); o0.y = tf32_rna(v1.x);   // k0,k4
        o0.z = tf32_rna(v0.y); o0.w = tf32_rna(v1.y);   // k1,k5
        o1.x = tf32_rna(v0.z); o1.y = tf32_rna(v1.z);   // k2,k6
        o1.z = tf32_rna(v0.w); o1.w = tf32_rna(v1.w);   // k3,k7
        float* dst = g_X + (size_t)kb * (N_DIM * 32) + (size_t)n * 32
                         + ((kk ^ (n & 3)) << 3);
        reinterpret_cast<float4*>(dst)[0] = o0;
        reinterpret_cast<float4*>(dst)[1] = o1;
    }
}

// ============================================================================
// Warp-specialized tf32 GEMM with cp.async.bulk producer.
// out[b,m,s] = sum_k W[m,k] * X[n,k] + bias[s],  n = b*2048 + s
// ============================================================================
__global__ void __launch_bounds__(THREADS, 1) gemm_kernel(
    const float* __restrict__ bias, float* __restrict__ out)
{
    extern __shared__ uint32_t smem[];
    const uint32_t sbase = smem_u32(smem);

    const int tid  = threadIdx.x;
    const int wid  = tid >> 5;
    const int lane = tid & 31;

    // CTA tile mapping: bid = mt + 32*nt (wave covers all m-tiles -> A reuse)
    const int mt = blockIdx.x & 31;
    const int nt = blockIdx.x >> 5;
    const int m0 = mt * BM;
    const int n0 = nt * BN;

    if (tid == 0) {
        #pragma unroll
        for (int s = 0; s < STAGES; s++) {
            MBARRIER_INIT(sbase + MB_FULL(s), 1);
            MBARRIER_INIT(sbase + MB_EMPTY(s), 8);
        }
    }
    __syncthreads();

    if (wid == 8) {
        // ------------------------- Producer warp -------------------------
        if (elect_one_pred()) {
            const float* Asrc0 = g_W + (size_t)m0 * 32;
            const float* Bsrc0 = g_X + (size_t)n0 * 32;
            int ph = 1;   // fresh barriers: parity-1 waits pass
            for (int ko = 0; ko < K_OUTER; ko++) {
                #pragma unroll
                for (int s = 0; s < STAGES; s++) {
                    const int k = ko * STAGES + s;
                    MBARRIER_WAIT_PARITY_RELAXED(sbase + MB_EMPTY(s), ph);
                    uint32_t full = sbase + MB_FULL(s);
                    uint32_t dst  = sbase + SMEM_STAGE0 + s * STAGE_BYTES;
                    MBARRIER_EXPECT_TX(full, STAGE_BYTES);
                    BULK_G2S(dst, Asrc0 + (size_t)k * (M_DIM * 32),
                             A_STAGE_BYTES, full);
                    BULK_G2S(dst + A_STAGE_BYTES, Bsrc0 + (size_t)k * (N_DIM * 32),
                             B_STAGE_BYTES, full);
                }
                ph ^= 1;
            }
        }
        return;
    }

    // --------------------------- Consumer warps ---------------------------
    const int g  = lane >> 2;       // fragment row group 0..7
    const int t  = lane & 3;        // fragment col group 0..3
    const int gx = g & 3;           // XOR swizzle key
    const int wm = wid & 1;         // warp m index 0..1
    const int wn = wid >> 1;        // warp n index 0..3

    // Per-kk base addresses (stage-0 A/B fragment bases; stage & mi/ni offsets
    // are compile-time immediates in the unrolled body — no inner-loop int math)
    uint32_t aAddr[4], bAddr[4];
    {
        const uint32_t aBase = sbase + SMEM_STAGE0
                             + (uint32_t)((wm * 64 + g) * 128 + t * 8);
        const uint32_t bBase = sbase + SMEM_STAGE0 + A_STAGE_BYTES
                             + (uint32_t)((wn * 64 + g) * 128 + t * 8);
        #pragma unroll
        for (int kk = 0; kk < 4; kk++) {
            const uint32_t kx = (uint32_t)(((kk ^ gx) & 3) << 5);
            aAddr[kk] = aBase + kx;
            bAddr[kk] = bBase + kx;
        }
    }

    float acc[4][8][4];
#pragma unroll
    for (int i = 0; i < 4; i++)
#pragma unroll
        for (int j = 0; j < 8; j++)
#pragma unroll
            for (int r = 0; r < 4; r++) acc[i][j][r] = 0.0f;

    int ph = 0;
    for (int ko = 0; ko < K_OUTER; ko++) {
        #pragma unroll
        for (int s = 0; s < STAGES; s++) {
            MBARRIER_WAIT_PARITY(sbase + MB_FULL(s), ph);
            const uint32_t soff = (uint32_t)(s * STAGE_BYTES);

            #pragma unroll
            for (int kk = 0; kk < 4; kk++) {
                uint2 alo[4], ahi[4];
                #pragma unroll
                for (int mi = 0; mi < 4; mi++) {
                    alo[mi] = lds64(aAddr[kk], soff + mi * 2048);
                    ahi[mi] = lds64(aAddr[kk], soff + mi * 2048 + 1024);
                }
                #pragma unroll
                for (int ni = 0; ni < 8; ni++) {
                    uint2 b = lds64(bAddr[kk], soff + ni * 1024);
                    #pragma unroll
                    for (int mi = 0; mi < 4; mi++) {
                        mma_tf32(acc[mi][ni], alo[mi].x, ahi[mi].x,
                                 alo[mi].y, ahi[mi].y, b.x, b.y);
                    }
                }
            }

            __syncwarp();
            if (lane == 0) MBARRIER_ARRIVE(sbase + MB_EMPTY(s));
        }
        ph ^= 1;
    }

    // ------------------------------------------------------------------------
    // Epilogue: out[b, m, s] = acc + bias[s]; CTA tile lies in one batch
    // ------------------------------------------------------------------------
    const int b   = n0 >> 11;        // n0 / 2048
    const int s0c = n0 & 2047;
    float* obase = out + (size_t)b * M_DIM * S_DIM;

#pragma unroll
    for (int mi = 0; mi < 4; mi++) {
#pragma unroll
        for (int ni = 0; ni < 8; ni++) {
            int sl = s0c + wn * 64 + ni * 8 + 2 * t;
            float2 bv = *reinterpret_cast<const float2*>(bias + sl);
            int m = m0 + wm * 64 + mi * 16 + g;

            float2 v0;
            v0.x = acc[mi][ni][0] + bv.x;
            v0.y = acc[mi][ni][1] + bv.y;
            *reinterpret_cast<float2*>(obase + (size_t)m * S_DIM + sl) = v0;

            float2 v1;
            v1.x = acc[mi][ni][2] + bv.x;
            v1.y = acc[mi][ni][3] + bv.y;
            *reinterpret_cast<float2*>(obase + (size_t)(m + 8) * S_DIM + sl) = v1;
        }
    }
}

// ============================================================================
// Host launch
// ============================================================================
extern "C" void kernel_launch(void* const* d_in, const int* in_sizes, int n_in,
                              void* d_out, int out_size) {
    const float* x      = (const float*)d_in[0];
    const float* values = (const float*)d_in[1];
    const float* bias   = (const float*)d_in[2];
    const int* row_ids  = (const int*)d_in[3];
    const int* col_idx  = (const int*)d_in[4];
    int nnz = in_sizes[1];
    float* out = (float*)d_out;

    void* wptr = nullptr;
    cudaGetSymbolAddress(&wptr, g_W);

    // 1) zero W (each replay re-accumulates from zero)
    cudaMemsetAsync(wptr, 0, (size_t)M_DIM * K_DIM * sizeof(float));

    // 2) scatter-add COO values directly into blocked+swizzled W
    scatter_kernel<<<(nnz + 255) / 256, 256>>>(values, row_ids, col_idx, nnz);

    // 3) tf32-round W in place; build blocked+swizzled tf32 X
    round_w_kernel<<<2048, 256>>>();
    conv_x_kernel<<<4096, 256>>>(x);

    // 4) GEMM
    cudaFuncSetAttribute(gemm_kernel,
                         cudaFuncAttributeMaxDynamicSharedMemorySize,
                         SMEM_BYTES);
    gemm_kernel<<<(M_DIM / BM) * (N_DIM / BN), THREADS, SMEM_BYTES>>>(bias, out);
}